// round 3
// baseline (speedup 1.0000x reference)
#include <cuda_runtime.h>
#include <cstdint>

// ---------------------------------------------------------------------------
// TT embedding:  VOC = 100^3,  EMB = 4*4*8 = 128,  RANK = 16
//   out[tok, n1*32+n2*8+n3] = sum_{r1,r2} core0[i1,n1,r1]*core1[r1,i2,n2,r2]*core2[r2,i3,n3]
// idx = i1*10000 + i2*100 + i3; idx==0 (PAD) -> zero row.
//
// Kernel 1: G01[i12][n1*64 + n2*16 + r2] = sum_r1 core0*core1 (10.2MB, L2-resident)
// Kernel 2: warp/token. G row loaded semi-coalesced (2x LDG.128/lane,
//           16 L1 wavefronts vs 32), missing quads fetched from the partner
//           lane via shfl.bfly. Packed f32x2 FMA. No shared memory.
// ---------------------------------------------------------------------------

#define VOC_LL 1000000ULL

__device__ float g_G01[10000 * 256];

// ---- packed fp32x2 helpers (sm_103a FFMA2) --------------------------------
__device__ __forceinline__ unsigned long long f32x2_fma(
    unsigned long long a, unsigned long long b, unsigned long long c)
{
    unsigned long long d;
    asm("fma.rn.f32x2 %0, %1, %2, %3;" : "=l"(d) : "l"(a), "l"(b), "l"(c));
    return d;
}
__device__ __forceinline__ unsigned long long f32x2_bcast(float x)
{
    unsigned long long d;
    asm("mov.b64 %0, {%1, %1};" : "=l"(d) : "f"(x));
    return d;
}
__device__ __forceinline__ float4 shfl_xor_f4(float4 v, int m)
{
    float4 r;
    r.x = __shfl_xor_sync(0xffffffffu, v.x, m);
    r.y = __shfl_xor_sync(0xffffffffu, v.y, m);
    r.z = __shfl_xor_sync(0xffffffffu, v.z, m);
    r.w = __shfl_xor_sync(0xffffffffu, v.w, m);
    return r;
}

// ---------------------------------------------------------------------------
// Kernel 1: G01 precompute.  grid=(100 [i2], 20 [i1-group of 5]), block=128.
// core0: (1,100,4,16)  elem (i1,n1,r1)    @ i1*64 + n1*16 + r1
// core1: (16,100,4,16) elem (r1,i2,n2,r2) @ r1*6400 + i2*64 + n2*16 + r2
// Thread p in [0,128): output pair p (elements 2p, 2p+1) for 5 i1's.
// ---------------------------------------------------------------------------
__global__ void __launch_bounds__(128) tt_precompute_g01(
    const float* __restrict__ core0,
    const float* __restrict__ core1)
{
    __shared__ float Bs[1024];   // core1 slice for this i2: [r1][n2*16+r2]
    __shared__ float As[320];    // core0 slices for 5 i1: [q][n1*16+r1]

    const int i2 = blockIdx.x;
    const int g  = blockIdx.y;   // i1 in [5g, 5g+5)
    const int p  = threadIdx.x;

    #pragma unroll
    for (int j = p; j < 1024; j += 128)
        Bs[j] = core1[(j >> 6) * 6400 + i2 * 64 + (j & 63)];
    #pragma unroll
    for (int j = p; j < 320; j += 128)
        As[j] = core0[g * 320 + j];
    __syncthreads();

    const int n1 = p >> 5;         // constant per warp -> As broadcast
    const int rp = (p & 31) * 2;   // rest pair start (n2*16+r2)

    unsigned long long b2[16];
    #pragma unroll
    for (int r1 = 0; r1 < 16; r1++)
        b2[r1] = *(const unsigned long long*)&Bs[r1 * 64 + rp];

    #pragma unroll
    for (int q = 0; q < 5; q++) {
        unsigned long long acc = 0;
        #pragma unroll
        for (int r1 = 0; r1 < 16; r1++)
            acc = f32x2_fma(f32x2_bcast(As[q * 64 + n1 * 16 + r1]), b2[r1], acc);
        const int i1 = g * 5 + q;
        *(unsigned long long*)&g_G01[((size_t)(i1 * 100 + i2)) * 256 + p * 2] = acc;
    }
}

// ---------------------------------------------------------------------------
// Kernel 2: gather.  1 warp per token, 4 outputs per lane.
// lane: row = lane>>1 (n1*4+n2), q = lane&1 (n3 quad).
// G granule g (16B) = row*4 + c.  Lane L loads granules 2L, 2L+1
// (= its own quads c=2q, 2q+1); quads c=2(1-q),2(1-q)+1 come from lane^1.
// core2: (16,100,8,1) elem (r2,i3,n3) @ r2*800 + i3*8 + n3
// ---------------------------------------------------------------------------
__global__ void __launch_bounds__(256) tt_gather(
    const void*  __restrict__ xraw,
    const float* __restrict__ core2,
    float*       __restrict__ out,
    int n_tok)
{
    const int t    = threadIdx.x;
    const int lane = t & 31;
    const int tok  = blockIdx.x * 8 + (t >> 5);
    if (tok >= n_tok) return;

    // --- index dtype autodetect (int64 declared, but jax may emit int32) ---
    const unsigned long long* p64 = (const unsigned long long*)xraw;
    bool is64 = true;
    #pragma unroll
    for (int j = 0; j < 4; j++)
        if (p64[j] >= VOC_LL) is64 = false;

    const long long idxll = is64 ? ((const long long*)xraw)[tok]
                                 : (long long)((const int*)xraw)[tok];
    const unsigned int iv  = (unsigned int)idxll;      // < 1e6
    const unsigned int i3  = iv % 100u;
    const unsigned int i12 = iv / 100u;

    const int row = lane >> 1;   // n1*4 + n2
    const int q   = lane & 1;    // n3 in [4q, 4q+4)

    // own quads: granules 2*lane, 2*lane+1  (quads c = 2q, 2q+1 of 'row')
    const float4* G = (const float4*)(g_G01 + (size_t)i12 * 256);
    const float4 ga = G[2 * lane];
    const float4 gb = G[2 * lane + 1];
    // partner quads via butterfly (lane^1 owns the other half of the row)
    const float4 pa = shfl_xor_f4(ga, 1);
    const float4 pb = shfl_xor_f4(gb, 1);

    // assemble gr[16]: r2-order = quads c=0..3 of this row
    const float4 c0 = q ? pa : ga;
    const float4 c1 = q ? pb : gb;
    const float4 c2 = q ? ga : pa;
    const float4 c3 = q ? gb : pb;
    const float gr[16] = { c0.x, c0.y, c0.z, c0.w,  c1.x, c1.y, c1.z, c1.w,
                           c2.x, c2.y, c2.z, c2.w,  c3.x, c3.y, c3.z, c3.w };

    // C: per r2 one 16B broadcast load (2 distinct addresses per warp)
    const char* cbase = (const char*)(core2 + (size_t)i3 * 8 + q * 4);
    unsigned long long acc0 = 0, acc1 = 0;
    #pragma unroll
    for (int r2 = 0; r2 < 16; r2++) {
        const ulonglong2 c = *(const ulonglong2*)(cbase + (size_t)r2 * 3200);
        const unsigned long long gg = f32x2_bcast(gr[r2]);
        acc0 = f32x2_fma(gg, c.x, acc0);
        acc1 = f32x2_fma(gg, c.y, acc1);
    }

    ulonglong2 res;
    res.x = acc0; res.y = acc1;
    if (iv == 0) { res.x = 0; res.y = 0; }   // PAD row
    *(ulonglong2*)(out + (size_t)tok * 128 + row * 8 + q * 4) = res;
}

// ---------------------------------------------------------------------------
extern "C" void kernel_launch(void* const* d_in, const int* in_sizes, int n_in,
                              void* d_out, int out_size)
{
    const void*  x     = d_in[0];
    const float* core0 = (const float*)d_in[1];
    const float* core1 = (const float*)d_in[2];
    const float* core2 = (const float*)d_in[3];
    float*       out   = (float*)d_out;

    const int n_tok = in_sizes[0];   // 32768

    tt_precompute_g01<<<dim3(100, 20), 128>>>(core0, core1);
    tt_gather<<<(n_tok + 7) / 8, 256>>>(x, core2, out, n_tok);
}